// round 4
// baseline (speedup 1.0000x reference)
#include <cuda_runtime.h>
#include <math.h>

#define BB 4
#define LL 8192
#define DD 2048
#define BLT (BB * LL)          // 32768 rows
#define CAP (LL / 2)           // 4096
#define NOISE_SCALE 0.1f
#define AUX_W 0.01f
#define CAP_F 0.5f

#define TPB   256
#define NBLK  (BLT / 8)        // 4096 matvec blocks, 8 rows each (1 row/warp)
#define NTAIL (BB + 1)         // 4 select blocks + 1 aux block
#define SEPT  (LL / TPB)       // 32 keys per thread in select phase

// Scratch (allocations forbidden)
__device__ unsigned g_keys[BLT];     // order-mapped noisy logits
__device__ float    g_part[NBLK];    // per-block sigmoid partial sums
__device__ unsigned g_done = 0;      // matvec completion counter (self-resetting)
__device__ unsigned g_fin  = 0;      // tail completion counter (self-resetting)

__global__ __launch_bounds__(TPB, 6) void fused_kernel(
    const float* __restrict__ x,
    const float* __restrict__ noise,
    const float* __restrict__ w,
    float* __restrict__ out)
{
    __shared__ float4   sw[DD / 4];      // 8 KB router weight
    __shared__ float    s_ws[8];
    __shared__ unsigned s_ticket;
    // tail-phase shared state
    __shared__ unsigned s_hist[256];
    __shared__ unsigned s_tot[8];
    __shared__ unsigned s_state[2];      // [0]=prefix, [1]=need
    __shared__ unsigned s_cnt;
    __shared__ int      s_eqn;
    __shared__ int      s_eqi[256];
    __shared__ double   s_dbw[8 * BB];   // per-warp per-batch aux partials

    const int t    = threadIdx.x;
    const int warp = t >> 5;
    const int lane = t & 31;
    const int bid  = blockIdx.x;

    // ================= phase 1: matvec (all 4096 blocks, multi-wave) =====
    const float4* w4 = reinterpret_cast<const float4*>(w);
    sw[t]       = w4[t];
    sw[t + 256] = w4[t + 256];
    __syncthreads();

    const int row = bid * 8 + warp;
    const float4* xr = reinterpret_cast<const float4*>(x + (size_t)row * DD);
    float acc = 0.0f;
#pragma unroll
    for (int j = 0; j < 16; j++) {
        const float4 xv = __ldg(&xr[lane + 32 * j]);
        const float4 wv = sw[lane + 32 * j];
        acc = fmaf(xv.x, wv.x, acc);
        acc = fmaf(xv.y, wv.y, acc);
        acc = fmaf(xv.z, wv.z, acc);
        acc = fmaf(xv.w, wv.w, acc);
    }
#pragma unroll
    for (int o = 16; o; o >>= 1) acc += __shfl_down_sync(0xffffffffu, acc, o);

    if (lane == 0) {
        out[BLT + row] = acc;                                // clean logit
        const float ny = fmaf(noise[row], NOISE_SCALE, acc); // noisy logit
        const unsigned b = __float_as_uint(ny);
        g_keys[row] = b ^ (((int)b >> 31) | 0x80000000u);    // monotone map
        s_ws[warp]  = 1.0f / (1.0f + expf(-acc));
    }
    __syncthreads();
    if (t == 0) {
        float s = 0.0f;
#pragma unroll
        for (int i = 0; i < 8; i++) s += s_ws[i];
        g_part[bid] = s;                 // plain store, no init needed
    }

    // publish writes, take a completion ticket
    __threadfence();
    __syncthreads();
    if (t == 0) s_ticket = atomicAdd(&g_done, 1u);
    __syncthreads();
    const unsigned ticket = s_ticket;
    if (ticket < NBLK - NTAIL) return;   // not a tail block

    // ================= tail handoff: last 5 finishers ====================
    if (t == 0) {
        while (*(volatile unsigned*)&g_done != NBLK) __nanosleep(32);
    }
    __syncthreads();
    __threadfence();                      // acquire all matvec results

    const int tail = (int)(ticket - (NBLK - NTAIL));   // 0..4

    if (tail == BB) {
        // ---------------- aux loss block -----------------------------
        double v[BB];
#pragma unroll
        for (int b = 0; b < BB; b++) {
            v[b] = (double)g_part[b * 1024 + t]
                 + (double)g_part[b * 1024 + 256 + t]
                 + (double)g_part[b * 1024 + 512 + t]
                 + (double)g_part[b * 1024 + 768 + t];
#pragma unroll
            for (int o = 16; o; o >>= 1)
                v[b] += __shfl_down_sync(0xffffffffu, v[b], o);
        }
        if (lane == 0)
#pragma unroll
            for (int b = 0; b < BB; b++) s_dbw[warp * BB + b] = v[b];
        __syncthreads();
        if (t == 0) {
            double a = 0.0;
#pragma unroll
            for (int b = 0; b < BB; b++) {
                double s = 0.0;
#pragma unroll
                for (int wq = 0; wq < 8; wq++) s += s_dbw[wq * BB + b];
                const double d = s / (double)LL - (double)CAP_F;
                a += d * d;
            }
            out[2 * BLT] = (float)((double)AUX_W * a / (double)BB);
        }
    } else {
        // ---------------- per-row top-CAP select (row = tail) --------
        const int srow = tail;
        const uint4* kr = reinterpret_cast<const uint4*>(g_keys + srow * LL);

        if (t == 0) { s_state[0] = 0u; s_state[1] = CAP; s_cnt = 0u; s_eqn = 0; }

        // 4-pass byte radix; keys re-read from L2 each pass (keeps regs low)
#pragma unroll
        for (int pass = 0; pass < 4; pass++) {
            const int s  = 24 - 8 * pass;
            const int hs = s + 8;
            s_hist[t] = 0u;
            __syncthreads();
            const unsigned prefix = s_state[0];
            const unsigned need   = s_state[1];
#pragma unroll
            for (int q = 0; q < SEPT / 4; q++) {
                const uint4 kv = __ldg(&kr[t * (SEPT / 4) + q]);
                const unsigned ks[4] = { kv.x, kv.y, kv.z, kv.w };
#pragma unroll
                for (int c = 0; c < 4; c++) {
                    if (pass == 0 || (((ks[c] ^ prefix) >> hs) == 0u))
                        atomicAdd(&s_hist[(ks[c] >> s) & 255u], 1u);
                }
            }
            __syncthreads();
            // cooperative suffix scan over 256 bins (8 warps)
            const unsigned h = s_hist[t];
            unsigned v = h;
#pragma unroll
            for (int o = 1; o < 32; o <<= 1) {
                const unsigned u = __shfl_down_sync(0xffffffffu, v, o);
                if (lane + o < 32) v += u;
            }
            if (lane == 0) s_tot[warp] = v;
            __syncthreads();
            unsigned carry = 0;
            for (int w2 = warp + 1; w2 < 8; w2++) carry += s_tot[w2];
            const unsigned S = v + carry;
            if (h > 0u && S >= need && (S - h) < need) {
                s_state[0] = prefix | ((unsigned)t << s);
                s_state[1] = need - (S - h);
            }
            __syncthreads();
        }
        const unsigned thr = s_state[0];   // exact CAP-th largest key

        // final pass: mask write + strict-greater count + tie collection
        float4* m4 = reinterpret_cast<float4*>(out + srow * LL);
        int cg = 0;
#pragma unroll
        for (int q = 0; q < SEPT / 4; q++) {
            const uint4 kv = __ldg(&kr[t * (SEPT / 4) + q]);
            const unsigned ks[4] = { kv.x, kv.y, kv.z, kv.w };
            float4 mv;
            mv.x = (ks[0] > thr) ? 1.0f : 0.0f;
            mv.y = (ks[1] > thr) ? 1.0f : 0.0f;
            mv.z = (ks[2] > thr) ? 1.0f : 0.0f;
            mv.w = (ks[3] > thr) ? 1.0f : 0.0f;
            m4[t * (SEPT / 4) + q] = mv;
            cg += (int)mv.x + (int)mv.y + (int)mv.z + (int)mv.w;
#pragma unroll
            for (int c = 0; c < 4; c++) {
                if (ks[c] == thr) {
                    const int p = atomicAdd(&s_eqn, 1);
                    if (p < 256) s_eqi[p] = t * SEPT + q * 4 + c;
                }
            }
        }
        cg = __reduce_add_sync(0xffffffffu, cg);
        if (lane == 0 && cg) atomicAdd(&s_cnt, (unsigned)cg);
        __syncthreads();

        // promote lowest-index ties to fill exactly CAP (jax top_k order)
        if (t == 0) {
            float* m = out + srow * LL;
            int need = CAP - (int)s_cnt;
            const int n = (s_eqn < 256) ? s_eqn : 256;
            for (int sel = 0; sel < need; sel++) {
                int best = 0x7fffffff, bi = -1;
                for (int q = 0; q < n; q++)
                    if (s_eqi[q] >= 0 && s_eqi[q] < best) { best = s_eqi[q]; bi = q; }
                if (bi < 0) break;
                m[best]   = 1.0f;
                s_eqi[bi] = -1;
            }
        }
    }

    // tail completion: last of the 5 resets counters for the next graph replay
    __syncthreads();
    if (t == 0) {
        const unsigned f = atomicAdd(&g_fin, 1u);
        if (f == NTAIL - 1) {
            g_fin = 0u;
            __threadfence();
            g_done = 0u;
        }
    }
}

// ---------------------------------------------------------------------------
extern "C" void kernel_launch(void* const* d_in, const int* in_sizes, int n_in,
                              void* d_out, int out_size)
{
    const float* x     = (const float*)d_in[0];
    const float* noise = (const float*)d_in[1];
    const float* w     = (const float*)d_in[2];
    float* out = (float*)d_out;   // [mask BL | logits BL | aux 1]
    (void)in_sizes; (void)n_in; (void)out_size;

    fused_kernel<<<NBLK, TPB>>>(x, noise, w, out);
}

// round 5
// speedup vs baseline: 1.1069x; 1.1069x over previous
#include <cuda_runtime.h>
#include <math.h>

#define BB 4
#define LL 8192
#define DD 2048
#define BLT (BB * LL)          // 32768 rows
#define CAP (LL / 2)           // 4096
#define NOISE_SCALE 0.1f
#define AUX_W 0.01f
#define CAP_F 0.5f

#define TPB   256
#define NBLK  (BLT / 8)        // 4096 blocks, 8 rows each (1 row/warp)
#define NTAIL (BB + 1)         // 4 select blocks + 1 aux block
#define SEPT  (LL / TPB)       // 32 keys per thread in select phase

// Scratch (allocations forbidden)
__device__ unsigned g_keys[BLT];
__device__ float    g_part[NBLK];
__device__ unsigned g_done = 0;     // self-resetting
__device__ unsigned g_fin  = 0;     // self-resetting

__global__ __launch_bounds__(TPB, 4) void fused_kernel(
    const float* __restrict__ x,
    const float* __restrict__ noise,
    const float* __restrict__ w,
    float* __restrict__ out)
{
    __shared__ float4   sw[DD / 4];      // 8 KB router weight
    __shared__ float    s_ws[8];
    __shared__ unsigned s_ticket;
    __shared__ unsigned s_hist[256];
    __shared__ unsigned s_tot[8];
    __shared__ unsigned s_state[2];      // [0]=prefix, [1]=need
    __shared__ unsigned s_cnt;
    __shared__ int      s_eqn;
    __shared__ int      s_eqi[256];
    __shared__ double   s_dbw[8 * BB];

    const int t    = threadIdx.x;
    const int warp = t >> 5;
    const int lane = t & 31;
    const int bid  = blockIdx.x;

    // ============ phase 1: matvec (explicit MLP-8 batched loads) =========
    const float4* w4 = reinterpret_cast<const float4*>(w);
    sw[t]       = w4[t];
    sw[t + 256] = w4[t + 256];
    __syncthreads();

    const int row = bid * 8 + warp;
    const float4* xr = reinterpret_cast<const float4*>(x + (size_t)row * DD);

    float4 b[8];
#pragma unroll
    for (int j = 0; j < 8; j++) b[j] = __ldg(&xr[lane + 32 * j]);

    float acc0 = 0.0f, acc1 = 0.0f;
#pragma unroll
    for (int j = 0; j < 8; j++) {
        const float4 wv = sw[lane + 32 * j];
        if (j & 1) {
            acc1 = fmaf(b[j].x, wv.x, acc1);
            acc1 = fmaf(b[j].y, wv.y, acc1);
            acc1 = fmaf(b[j].z, wv.z, acc1);
            acc1 = fmaf(b[j].w, wv.w, acc1);
        } else {
            acc0 = fmaf(b[j].x, wv.x, acc0);
            acc0 = fmaf(b[j].y, wv.y, acc0);
            acc0 = fmaf(b[j].z, wv.z, acc0);
            acc0 = fmaf(b[j].w, wv.w, acc0);
        }
    }
#pragma unroll
    for (int j = 0; j < 8; j++) b[j] = __ldg(&xr[lane + 32 * (j + 8)]);
#pragma unroll
    for (int j = 0; j < 8; j++) {
        const float4 wv = sw[lane + 32 * (j + 8)];
        if (j & 1) {
            acc1 = fmaf(b[j].x, wv.x, acc1);
            acc1 = fmaf(b[j].y, wv.y, acc1);
            acc1 = fmaf(b[j].z, wv.z, acc1);
            acc1 = fmaf(b[j].w, wv.w, acc1);
        } else {
            acc0 = fmaf(b[j].x, wv.x, acc0);
            acc0 = fmaf(b[j].y, wv.y, acc0);
            acc0 = fmaf(b[j].z, wv.z, acc0);
            acc0 = fmaf(b[j].w, wv.w, acc0);
        }
    }
    float acc = acc0 + acc1;
#pragma unroll
    for (int o = 16; o; o >>= 1) acc += __shfl_down_sync(0xffffffffu, acc, o);

    if (lane == 0) {
        out[BLT + row] = acc;                                // clean logit
        const float ny = fmaf(noise[row], NOISE_SCALE, acc); // noisy logit
        const unsigned nb = __float_as_uint(ny);
        g_keys[row] = nb ^ (((int)nb >> 31) | 0x80000000u);  // monotone map
        s_ws[warp]  = 1.0f / (1.0f + expf(-acc));
    }
    __syncthreads();
    if (t == 0) {
        float s = 0.0f;
#pragma unroll
        for (int i = 0; i < 8; i++) s += s_ws[i];
        g_part[bid] = s;
    }

    // publish + take completion ticket
    __threadfence();
    __syncthreads();
    if (t == 0) s_ticket = atomicAdd(&g_done, 1u);
    __syncthreads();
    const unsigned ticket = s_ticket;
    if (ticket < NBLK - NTAIL) return;

    // ============ tail handoff: last 5 finishers =========================
    if (t == 0) {
        while (*(volatile unsigned*)&g_done != NBLK) __nanosleep(32);
    }
    __syncthreads();
    __threadfence();

    const int tail = (int)(ticket - (NBLK - NTAIL));   // 0..4

    if (tail == BB) {
        // ---------------- aux loss ----------------
        double v[BB];
#pragma unroll
        for (int bq = 0; bq < BB; bq++) {
            v[bq] = (double)g_part[bq * 1024 + t]
                  + (double)g_part[bq * 1024 + 256 + t]
                  + (double)g_part[bq * 1024 + 512 + t]
                  + (double)g_part[bq * 1024 + 768 + t];
#pragma unroll
            for (int o = 16; o; o >>= 1)
                v[bq] += __shfl_down_sync(0xffffffffu, v[bq], o);
        }
        if (lane == 0)
#pragma unroll
            for (int bq = 0; bq < BB; bq++) s_dbw[warp * BB + bq] = v[bq];
        __syncthreads();
        if (t == 0) {
            double a = 0.0;
#pragma unroll
            for (int bq = 0; bq < BB; bq++) {
                double s = 0.0;
#pragma unroll
                for (int wq = 0; wq < 8; wq++) s += s_dbw[wq * BB + bq];
                const double d = s / (double)LL - (double)CAP_F;
                a += d * d;
            }
            out[2 * BLT] = (float)((double)AUX_W * a / (double)BB);
        }
    } else {
        // ---------------- per-row top-CAP select (register-resident) -----
        const int srow = tail;
        unsigned k[SEPT];
        {
            const uint4* kr = reinterpret_cast<const uint4*>(g_keys + srow * LL);
#pragma unroll
            for (int q = 0; q < SEPT / 4; q++) {
                const uint4 v = __ldg(&kr[t * (SEPT / 4) + q]);
                k[q * 4 + 0] = v.x; k[q * 4 + 1] = v.y;
                k[q * 4 + 2] = v.z; k[q * 4 + 3] = v.w;
            }
        }
        if (t == 0) { s_state[0] = 0u; s_state[1] = CAP; s_cnt = 0u; s_eqn = 0; }

        // 4-pass byte radix; passes 1-3 prefix-filtered (few participants)
#pragma unroll
        for (int pass = 0; pass < 4; pass++) {
            const int s  = 24 - 8 * pass;
            const int hs = (pass == 0) ? 0 : (s + 8);
            s_hist[t] = 0u;
            __syncthreads();
            const unsigned prefix = s_state[0];
            const unsigned need   = s_state[1];
#pragma unroll
            for (int j = 0; j < SEPT; j++) {
                if (pass == 0 || (((k[j] ^ prefix) >> hs) == 0u))
                    atomicAdd(&s_hist[(k[j] >> s) & 255u], 1u);
            }
            __syncthreads();
            // cooperative suffix scan over 256 bins (8 warps)
            const unsigned h = s_hist[t];
            unsigned v = h;
#pragma unroll
            for (int o = 1; o < 32; o <<= 1) {
                const unsigned u = __shfl_down_sync(0xffffffffu, v, o);
                if (lane + o < 32) v += u;
            }
            if (lane == 0) s_tot[warp] = v;
            __syncthreads();
            unsigned carry = 0;
#pragma unroll
            for (int w2 = 0; w2 < 8; w2++) if (w2 > warp) carry += s_tot[w2];
            const unsigned S = v + carry;
            if (h > 0u && S >= need && (S - h) < need) {
                s_state[0] = prefix | ((unsigned)t << s);
                s_state[1] = need - (S - h);
            }
            __syncthreads();
        }
        const unsigned thr = s_state[0];   // exact CAP-th largest key

        // mask write + strict-greater count + tie collection (from regs)
        float4* m4 = reinterpret_cast<float4*>(out + srow * LL);
        int cg = 0;
#pragma unroll
        for (int q = 0; q < SEPT / 4; q++) {
            float4 mv;
            mv.x = (k[q * 4 + 0] > thr) ? 1.0f : 0.0f;
            mv.y = (k[q * 4 + 1] > thr) ? 1.0f : 0.0f;
            mv.z = (k[q * 4 + 2] > thr) ? 1.0f : 0.0f;
            mv.w = (k[q * 4 + 3] > thr) ? 1.0f : 0.0f;
            m4[t * (SEPT / 4) + q] = mv;
            cg += (int)mv.x + (int)mv.y + (int)mv.z + (int)mv.w;
#pragma unroll
            for (int c = 0; c < 4; c++) {
                if (k[q * 4 + c] == thr) {
                    const int p = atomicAdd(&s_eqn, 1);
                    if (p < 256) s_eqi[p] = t * SEPT + q * 4 + c;
                }
            }
        }
        cg = __reduce_add_sync(0xffffffffu, cg);
        if (lane == 0 && cg) atomicAdd(&s_cnt, (unsigned)cg);
        __syncthreads();

        // promote lowest-index ties to fill exactly CAP (jax top_k order)
        if (t == 0) {
            float* m = out + srow * LL;
            int need = CAP - (int)s_cnt;
            const int n = (s_eqn < 256) ? s_eqn : 256;
            for (int sel = 0; sel < need; sel++) {
                int best = 0x7fffffff, bi = -1;
                for (int q = 0; q < n; q++)
                    if (s_eqi[q] >= 0 && s_eqi[q] < best) { best = s_eqi[q]; bi = q; }
                if (bi < 0) break;
                m[best]   = 1.0f;
                s_eqi[bi] = -1;
            }
        }
    }

    // last tail block resets counters for next graph replay
    __syncthreads();
    if (t == 0) {
        const unsigned f = atomicAdd(&g_fin, 1u);
        if (f == NTAIL - 1) {
            g_fin = 0u;
            __threadfence();
            g_done = 0u;
        }
    }
}

// ---------------------------------------------------------------------------
extern "C" void kernel_launch(void* const* d_in, const int* in_sizes, int n_in,
                              void* d_out, int out_size)
{
    const float* x     = (const float*)d_in[0];
    const float* noise = (const float*)d_in[1];
    const float* w     = (const float*)d_in[2];
    float* out = (float*)d_out;   // [mask BL | logits BL | aux 1]
    (void)in_sizes; (void)n_in; (void)out_size;

    fused_kernel<<<NBLK, TPB>>>(x, noise, w, out);
}

// round 6
// speedup vs baseline: 1.2378x; 1.1183x over previous
#include <cuda_runtime.h>
#include <math.h>

#define BB 4
#define LL 8192
#define DD 2048
#define BLT (BB * LL)          // 32768 rows
#define CAP (LL / 2)           // 4096
#define NOISE_SCALE 0.1f
#define AUX_W 0.01f
#define CAP_F 0.5f

#define TPB  256
#define NBLK (BLT / 8)         // 4096 matvec blocks, 1 row/warp
#define SEPT (LL / TPB)        // 32 keys per thread in select

// Scratch (allocations forbidden)
__device__ unsigned g_keys[BLT];     // order-mapped noisy logits
__device__ float    g_part[NBLK];    // per-block sigmoid partials

// ---------------------------------------------------------------------------
// Kernel 1: router matvec — pure HBM stream, no in-kernel sync machinery.
// ---------------------------------------------------------------------------
__global__ __launch_bounds__(TPB) void matvec_kernel(
    const float* __restrict__ x,
    const float* __restrict__ noise,
    const float* __restrict__ w,
    float* __restrict__ out)
{
    __shared__ float4 sw[DD / 4];     // 8 KB router weight
    __shared__ float  ssig[8];

    const int t = threadIdx.x;
    const float4* w4 = reinterpret_cast<const float4*>(w);
    sw[t]       = w4[t];
    sw[t + 256] = w4[t + 256];
    __syncthreads();

    const int warp = t >> 5;
    const int lane = t & 31;
    const int row  = blockIdx.x * 8 + warp;

    const float4* xr = reinterpret_cast<const float4*>(x + (size_t)row * DD);
    float acc = 0.0f;
#pragma unroll
    for (int j = 0; j < 16; j++) {
        const float4 xv = __ldg(&xr[lane + 32 * j]);
        const float4 wv = sw[lane + 32 * j];
        acc = fmaf(xv.x, wv.x, acc);
        acc = fmaf(xv.y, wv.y, acc);
        acc = fmaf(xv.z, wv.z, acc);
        acc = fmaf(xv.w, wv.w, acc);
    }
#pragma unroll
    for (int o = 16; o; o >>= 1) acc += __shfl_down_sync(0xffffffffu, acc, o);

    if (lane == 0) {
        out[BLT + row] = acc;                                // clean logit
        const float ny = fmaf(noise[row], NOISE_SCALE, acc); // noisy logit
        const unsigned nb = __float_as_uint(ny);
        g_keys[row] = nb ^ (((int)nb >> 31) | 0x80000000u);  // monotone map
        ssig[warp]  = 1.0f / (1.0f + expf(-acc));
    }
    __syncthreads();
    if (t == 0) {
        float s = 0.0f;
#pragma unroll
        for (int i = 0; i < 8; i++) s += ssig[i];
        g_part[blockIdx.x] = s;      // plain store, no init needed
    }
}

// ---------------------------------------------------------------------------
// Kernel 2: blocks 0..3 = per-row top-CAP select (register-resident,
// prefix-filtered byte radix); block 4 = aux loss.
// ---------------------------------------------------------------------------
__global__ __launch_bounds__(TPB) void select_aux_kernel(float* __restrict__ out)
{
    __shared__ unsigned s_hist[256];
    __shared__ unsigned s_tot[8];
    __shared__ unsigned s_state[2];   // [0]=prefix, [1]=need
    __shared__ unsigned s_cnt;
    __shared__ int      s_eqn;
    __shared__ int      s_eqi[256];
    __shared__ double   s_dbw[8 * BB];

    const int t    = threadIdx.x;
    const int warp = t >> 5;
    const int lane = t & 31;
    const int bid  = blockIdx.x;

    if (bid == BB) {
        // ---------------- aux loss ----------------
        double v[BB];
#pragma unroll
        for (int bq = 0; bq < BB; bq++) {
            v[bq] = (double)g_part[bq * 1024 + t]
                  + (double)g_part[bq * 1024 + 256 + t]
                  + (double)g_part[bq * 1024 + 512 + t]
                  + (double)g_part[bq * 1024 + 768 + t];
#pragma unroll
            for (int o = 16; o; o >>= 1)
                v[bq] += __shfl_down_sync(0xffffffffu, v[bq], o);
        }
        if (lane == 0)
#pragma unroll
            for (int bq = 0; bq < BB; bq++) s_dbw[warp * BB + bq] = v[bq];
        __syncthreads();
        if (t == 0) {
            double a = 0.0;
#pragma unroll
            for (int bq = 0; bq < BB; bq++) {
                double s = 0.0;
#pragma unroll
                for (int wq = 0; wq < 8; wq++) s += s_dbw[wq * BB + bq];
                const double d = s / (double)LL - (double)CAP_F;
                a += d * d;
            }
            out[2 * BLT] = (float)((double)AUX_W * a / (double)BB);
        }
        return;
    }

    // ---------------- per-row top-CAP select ----------------
    const int srow = bid;
    unsigned k[SEPT];
    {
        const uint4* kr = reinterpret_cast<const uint4*>(g_keys + srow * LL);
#pragma unroll
        for (int q = 0; q < SEPT / 4; q++) {
            const uint4 v = __ldg(&kr[t * (SEPT / 4) + q]);
            k[q * 4 + 0] = v.x; k[q * 4 + 1] = v.y;
            k[q * 4 + 2] = v.z; k[q * 4 + 3] = v.w;
        }
    }
    if (t == 0) { s_state[0] = 0u; s_state[1] = CAP; s_cnt = 0u; s_eqn = 0; }

    // 4-pass byte radix; passes 1-3 prefix-filtered (few participants)
#pragma unroll
    for (int pass = 0; pass < 4; pass++) {
        const int s  = 24 - 8 * pass;
        const int hs = (pass == 0) ? 0 : (s + 8);
        s_hist[t] = 0u;
        __syncthreads();
        const unsigned prefix = s_state[0];
        const unsigned need   = s_state[1];
#pragma unroll
        for (int j = 0; j < SEPT; j++) {
            if (pass == 0 || (((k[j] ^ prefix) >> hs) == 0u))
                atomicAdd(&s_hist[(k[j] >> s) & 255u], 1u);
        }
        __syncthreads();
        // cooperative suffix scan over 256 bins (8 warps of 32)
        const unsigned h = s_hist[t];
        unsigned v = h;
#pragma unroll
        for (int o = 1; o < 32; o <<= 1) {
            const unsigned u = __shfl_down_sync(0xffffffffu, v, o);
            if (lane + o < 32) v += u;
        }
        if (lane == 0) s_tot[warp] = v;
        __syncthreads();
        unsigned carry = 0;
#pragma unroll
        for (int w2 = 0; w2 < 8; w2++) if (w2 > warp) carry += s_tot[w2];
        const unsigned S = v + carry;                 // suffix incl. own bin
        if (h > 0u && S >= need && (S - h) < need) {
            s_state[0] = prefix | ((unsigned)t << s);
            s_state[1] = need - (S - h);
        }
        __syncthreads();
    }
    const unsigned thr = s_state[0];                  // exact CAP-th largest

    // mask write + strict-greater count + tie collection (from registers)
    float4* m4 = reinterpret_cast<float4*>(out + srow * LL);
    int cg = 0;
#pragma unroll
    for (int q = 0; q < SEPT / 4; q++) {
        float4 mv;
        mv.x = (k[q * 4 + 0] > thr) ? 1.0f : 0.0f;
        mv.y = (k[q * 4 + 1] > thr) ? 1.0f : 0.0f;
        mv.z = (k[q * 4 + 2] > thr) ? 1.0f : 0.0f;
        mv.w = (k[q * 4 + 3] > thr) ? 1.0f : 0.0f;
        m4[t * (SEPT / 4) + q] = mv;
        cg += (int)mv.x + (int)mv.y + (int)mv.z + (int)mv.w;
#pragma unroll
        for (int c = 0; c < 4; c++) {
            if (k[q * 4 + c] == thr) {
                const int p = atomicAdd(&s_eqn, 1);
                if (p < 256) s_eqi[p] = t * SEPT + q * 4 + c;
            }
        }
    }
    cg = __reduce_add_sync(0xffffffffu, cg);
    if (lane == 0 && cg) atomicAdd(&s_cnt, (unsigned)cg);
    __syncthreads();

    // promote lowest-index ties to fill exactly CAP (jax top_k order)
    if (t == 0) {
        float* m = out + srow * LL;
        int need = CAP - (int)s_cnt;
        const int n = (s_eqn < 256) ? s_eqn : 256;
        for (int sel = 0; sel < need; sel++) {
            int best = 0x7fffffff, bi = -1;
            for (int q = 0; q < n; q++)
                if (s_eqi[q] >= 0 && s_eqi[q] < best) { best = s_eqi[q]; bi = q; }
            if (bi < 0) break;
            m[best]   = 1.0f;
            s_eqi[bi] = -1;
        }
    }
}

// ---------------------------------------------------------------------------
extern "C" void kernel_launch(void* const* d_in, const int* in_sizes, int n_in,
                              void* d_out, int out_size)
{
    const float* x     = (const float*)d_in[0];
    const float* noise = (const float*)d_in[1];
    const float* w     = (const float*)d_in[2];
    float* out = (float*)d_out;   // [mask BL | logits BL | aux 1]
    (void)in_sizes; (void)n_in; (void)out_size;

    matvec_kernel<<<NBLK, TPB>>>(x, noise, w, out);
    select_aux_kernel<<<BB + 1, TPB>>>(out);
}